// round 1
// baseline (speedup 1.0000x reference)
#include <cuda_runtime.h>
#include <cuda_bf16.h>

// Problem constants (from reference): N=32, M=24, NS=4, H=256,
// ALPHA=0.1, SLACK_PEN=1, LOWER=0, RHO=1, ITERS=200.
//
// Strategy: one warp per (B*S) problem. Constraint rows are permuted
// (permutation-invariant for ADMM) so the 32 "-I" (x>=0) rows live at
// lane t ("lo") and the 24 A rows + 4 slack rows + 4 zero-pad rows live
// at lane t ("hi"). The 4 slack variables are eliminated by Schur
// complement (D = 4I), so the per-iteration solve is a 32x32 mat-vec
// with K = (A_h'A_h + 0.75 A_s'A_s + 2I)^-1 held in registers.
// v = A*u is fused as (A*K)*tmp so both mat-vecs share one broadcast.

#define WARPS_PER_CTA 12
#define NTHREADS (WARPS_PER_CTA * 32)
#define ADMM_ITERS 200
#define FULLMASK 0xffffffffu

// smem layout (floats): W1 [32][257], w2[256], b1[256], then per-warp:
// sA [24][33], sM [32][36], sAK [24][33]  = 2736 floats/warp
#define SM_W1    (32 * 257)
#define SM_WARP  (24*33 + 32*36 + 24*33)
#define SMEM_FLOATS (SM_W1 + 256 + 256 + WARPS_PER_CTA * SM_WARP)
#define SMEM_BYTES (SMEM_FLOATS * 4)

__device__ __forceinline__ float bcast(float v, int lane) {
    return __shfl_sync(FULLMASK, v, lane & 31);
}

// In-place Gauss-Jordan inverse of SPD 32x32 matrix, row stride 36 floats
// (float4-friendly, (4i+j)%32 banking => conflict wavefronts == bandwidth floor).
__device__ void invert32(float* sM, int t) {
    #pragma unroll 1
    for (int k = 0; k < 32; k++) {
        float piv  = sM[k*36 + k];
        float pinv = 1.0f / piv;
        float rk = sM[k*36 + t] * pinv;
        if (t == k) rk = pinv;
        __syncwarp();
        sM[k*36 + t] = rk;
        __syncwarp();
        if (t != k) {
            float f = sM[t*36 + k];
            float4* rowT = reinterpret_cast<float4*>(sM + t*36);
            const float4* rowK = reinterpret_cast<const float4*>(sM + k*36);
            #pragma unroll
            for (int j4 = 0; j4 < 8; j4++) {
                float4 a = rowT[j4];
                float4 bb = rowK[j4];
                a.x -= f * bb.x; a.y -= f * bb.y;
                a.z -= f * bb.z; a.w -= f * bb.w;
                rowT[j4] = a;
            }
            sM[t*36 + k] = -f * pinv;   // inverse column fix-up
        }
        __syncwarp();
    }
}

__global__ __launch_bounds__(NTHREADS, 1)
void fw_kernel(const float* __restrict__ g_x,  const float* __restrict__ g_A,
               const float* __restrict__ g_b,  const float* __restrict__ g_W1,
               const float* __restrict__ g_b1, const float* __restrict__ g_w2,
               float* __restrict__ g_out, int nprob)
{
    extern __shared__ float smem[];
    float* sW1 = smem;               // [32][257] padded
    float* sw2 = sW1 + SM_W1;        // [256]
    float* sb1 = sw2 + 256;          // [256]
    float* wsp = sb1 + 256;

    const int tid = threadIdx.x;
    const int wid = tid >> 5;
    const int t   = tid & 31;

    for (int i = tid; i < 32 * 256; i += NTHREADS)
        sW1[(i >> 8) * 257 + (i & 255)] = g_W1[i];
    for (int i = tid; i < 256; i += NTHREADS) { sw2[i] = g_w2[i]; sb1[i] = g_b1[i]; }
    __syncthreads();

    const int p = blockIdx.x * WARPS_PER_CTA + wid;
    if (p >= nprob) return;

    float* sA  = wsp + wid * SM_WARP;   // [24][33]
    float* sM  = sA + 24 * 33;          // [32][36]
    float* sAK = sM + 32 * 36;          // [24][33]

    const float* Ap = g_A + (size_t)p * 768;   // [24][32] row-major
    float Acol[24];                              // column t of A
    #pragma unroll
    for (int r = 0; r < 24; r++) {
        float v = Ap[r * 32 + t];
        Acol[r] = v;
        sA[r * 33 + t] = v;
    }
    const float h_hi = (t < 24) ? g_b[p * 24 + t] : 0.0f;
    const float xr   = g_x[(size_t)p * 32 + t];
    __syncwarp();

    // ===== anchor: Schur matrix S = Ah'Ah + 0.75*As'As + 2I, K = S^-1 =====
    {
        float Bcol[24];
        #pragma unroll
        for (int r = 0; r < 24; r++) Bcol[r] = Acol[r] * ((r < 20) ? 1.0f : 0.75f);
        #pragma unroll 1
        for (int i = 0; i < 32; i++) {
            float acc = (i == t) ? 2.0f : 0.0f;
            #pragma unroll
            for (int r = 0; r < 24; r++) acc += Bcol[r] * sA[r * 33 + i];
            sM[i * 36 + t] = acc;       // S[i][t]
        }
    }
    __syncwarp();
    invert32(sM, t);                     // sM = K

    float Krow[32], AKrow[32];
    #pragma unroll
    for (int j = 0; j < 32; j++) Krow[j] = sM[t * 36 + j];
    #pragma unroll 1
    for (int r = 0; r < 24; r++) {       // AK = A * K  (24x32)
        float acc = 0.0f;
        #pragma unroll 1
        for (int i = 0; i < 32; i++) acc += sA[r * 33 + i] * sM[i * 36 + t];
        sAK[r * 33 + t] = acc;
    }
    __syncwarp();
    #pragma unroll
    for (int j = 0; j < 32; j++) AKrow[j] = (t < 24) ? sAK[t * 33 + j] : 0.0f;

    // ===== anchor ADMM (rho = 1) =====
    float z_lo = 0.f, z_hi = 0.f, y_lo = 0.f, y_hi = 0.f;
    #pragma unroll 1
    for (int it = 0; it < ADMM_ITERS; it++) {
        float w_lo = z_lo - y_lo;
        float w_hi = z_hi - y_hi;
        // rhs_x = x_raw - w_lo + A' * w_hi[0..23]
        float rx0 = xr - w_lo, rx1 = 0.f;
        #pragma unroll
        for (int r = 0; r < 24; r += 2) {
            rx0 += Acol[r]     * bcast(w_hi, r);
            rx1 += Acol[r + 1] * bcast(w_hi, r + 1);
        }
        // rhs_s[j] = -w_hi[20+j] - w_hi[24+j]  (lanes 0..3 meaningful)
        float rs  = -bcast(w_hi, 20 + t) - bcast(w_hi, 24 + t);
        float rs4 = 0.25f * rs;
        float tmp = rx0 + rx1;           // tmp = rhs_x + 0.25 * As' * rhs_s
        #pragma unroll
        for (int j = 0; j < 4; j++) tmp += Acol[20 + j] * bcast(rs4, j);
        // u = K*tmp ; v = A*u = (A*K)*tmp   (shared broadcasts)
        float u0 = 0, u1 = 0, v0 = 0, v1 = 0;
        #pragma unroll
        for (int j = 0; j < 32; j += 2) {
            float a  = bcast(tmp, j);
            float b2 = bcast(tmp, j + 1);
            u0 += Krow[j]     * a;  v0 += AKrow[j]     * a;
            u1 += Krow[j + 1] * b2; v1 += AKrow[j + 1] * b2;
        }
        float u = u0 + u1, v = v0 + v1;
        // u_s[j] = 0.25*(rs[j] + v[20+j])  (lanes 0..3)
        float us  = 0.25f * (rs + bcast(v, 20 + t));
        float usa = bcast(us, t - 20);   // for lanes 20..23
        float usb = bcast(us, t - 24);   // for lanes 24..27
        float Gu_hi = (t < 20) ? v : (t < 24) ? (v - usa) : (t < 28) ? (-usb) : 0.0f;
        float zn = fminf(Gu_hi + y_hi, h_hi);
        y_hi += Gu_hi - zn; z_hi = zn;
        float zl = fminf(y_lo - u, 0.0f);   // Gu_lo = -u, h_lo = 0
        y_lo += (-u) - zl;  z_lo = zl;
    }
    float x_feas;
    {   // final half-step: u from final (z, y)
        float w_lo = z_lo - y_lo;
        float w_hi = z_hi - y_hi;
        float rx = xr - w_lo;
        #pragma unroll
        for (int r = 0; r < 24; r++) rx += Acol[r] * bcast(w_hi, r);
        float rs  = -bcast(w_hi, 20 + t) - bcast(w_hi, 24 + t);
        float rs4 = 0.25f * rs;
        float tmp = rx;
        #pragma unroll
        for (int j = 0; j < 4; j++) tmp += Acol[20 + j] * bcast(rs4, j);
        float u = 0.f;
        #pragma unroll
        for (int j = 0; j < 32; j++) u += Krow[j] * bcast(tmp, j);
        x_feas = u;
    }

    // ===== critic gradient: g = W1 @ (w2 * (1 - tanh(xW1+b1)^2)) =====
    float gsum = 0.f;
    {
        float pre[8];
        #pragma unroll
        for (int k2 = 0; k2 < 8; k2++) pre[k2] = sb1[k2 * 32 + t];
        #pragma unroll 1
        for (int n = 0; n < 32; n++) {
            float xv = bcast(x_feas, n);
            #pragma unroll
            for (int k2 = 0; k2 < 8; k2++)
                pre[k2] += sW1[n * 257 + k2 * 32 + t] * xv;
        }
        float coef[8];
        #pragma unroll
        for (int k2 = 0; k2 < 8; k2++) {
            float th = tanhf(pre[k2]);
            coef[k2] = sw2[k2 * 32 + t] * (1.0f - th * th);
        }
        #pragma unroll 1
        for (int l = 0; l < 32; l++) {
            #pragma unroll
            for (int k2 = 0; k2 < 8; k2++)
                gsum += sW1[t * 257 + k2 * 32 + l] * bcast(coef[k2], l);
        }
    }

    // ===== lmo: M = A'A + I, invert; AM = A*M^-1 =====
    __syncwarp();
    #pragma unroll 1
    for (int i = 0; i < 32; i++) {
        float acc = (i == t) ? 1.0f : 0.0f;
        #pragma unroll
        for (int r = 0; r < 24; r++) acc += Acol[r] * sA[r * 33 + i];
        sM[i * 36 + t] = acc;
    }
    __syncwarp();
    invert32(sM, t);
    #pragma unroll
    for (int j = 0; j < 32; j++) Krow[j] = sM[t * 36 + j];
    #pragma unroll 1
    for (int r = 0; r < 24; r++) {
        float acc = 0.0f;
        #pragma unroll 1
        for (int i = 0; i < 32; i++) acc += sA[r * 33 + i] * sM[i * 36 + t];
        sAK[r * 33 + t] = acc;
    }
    __syncwarp();
    #pragma unroll
    for (int j = 0; j < 32; j++) AKrow[j] = (t < 24) ? sAK[t * 33 + j] : 0.0f;

    // ===== lmo ADMM (q = -g  =>  rhs = g + G'w) =====
    z_lo = 0.f; z_hi = 0.f; y_lo = 0.f; y_hi = 0.f;
    #pragma unroll 1
    for (int it = 0; it < ADMM_ITERS; it++) {
        float w_lo = z_lo - y_lo;
        float w_hi = z_hi - y_hi;
        float r0 = gsum - w_lo, r1 = 0.f;
        #pragma unroll
        for (int r = 0; r < 24; r += 2) {
            r0 += Acol[r]     * bcast(w_hi, r);
            r1 += Acol[r + 1] * bcast(w_hi, r + 1);
        }
        float rhs = r0 + r1;
        float u0 = 0, u1 = 0, v0 = 0, v1 = 0;
        #pragma unroll
        for (int j = 0; j < 32; j += 2) {
            float a  = bcast(rhs, j);
            float b2 = bcast(rhs, j + 1);
            u0 += Krow[j]     * a;  v0 += AKrow[j]     * a;
            u1 += Krow[j + 1] * b2; v1 += AKrow[j + 1] * b2;
        }
        float u = u0 + u1, v = v0 + v1;
        float zn = fminf(v + y_hi, h_hi);       // A rows: Gu = v
        y_hi += v - zn; z_hi = zn;
        float zl = fminf(y_lo - u, 0.0f);       // -I rows: Gu = -u
        y_lo += (-u) - zl; z_lo = zl;
    }
    float c;
    {
        float w_lo = z_lo - y_lo;
        float w_hi = z_hi - y_hi;
        float rhs = gsum - w_lo;
        #pragma unroll
        for (int r = 0; r < 24; r++) rhs += Acol[r] * bcast(w_hi, r);
        float u = 0.f;
        #pragma unroll
        for (int j = 0; j < 32; j++) u += Krow[j] * bcast(rhs, j);
        c = u;
    }

    // x_fw = (1 - ALPHA)*x_feas + ALPHA*c
    g_out[(size_t)p * 32 + t] = 0.9f * x_feas + 0.1f * c;
}

extern "C" void kernel_launch(void* const* d_in, const int* in_sizes, int n_in,
                              void* d_out, int out_size)
{
    const float* x  = (const float*)d_in[0];
    const float* A  = (const float*)d_in[1];
    const float* b  = (const float*)d_in[2];
    const float* W1 = (const float*)d_in[3];
    const float* b1 = (const float*)d_in[4];
    const float* w2 = (const float*)d_in[5];

    int nprob = in_sizes[0] / 32;   // B*S problems of N=32 vars
    cudaFuncSetAttribute(fw_kernel, cudaFuncAttributeMaxDynamicSharedMemorySize,
                         SMEM_BYTES);
    int grid = (nprob + WARPS_PER_CTA - 1) / WARPS_PER_CTA;
    fw_kernel<<<grid, NTHREADS, SMEM_BYTES>>>(x, A, b, W1, b1, w2,
                                              (float*)d_out, nprob);
}

// round 8
// speedup vs baseline: 1.4463x; 1.4463x over previous
#include <cuda_runtime.h>

// N=32, M=24, NS=4, H=256, ALPHA=0.1, SLACK_PEN=1, LOWER=0, RHO=1, ITERS=200.
// One warp per problem. Row permutation: 32 "-I" rows -> "lo" scalar per lane,
// 24 A rows + 4 slack + 4 pad -> "hi" scalar per lane. Slacks eliminated via
// Schur complement (D = 4I). Per-iteration: broadcast via SMEM staging
// (1 STS + broadcast LDS.128), math via packed fma.rn.f32x2.

#define WARPS_PER_CTA 12
#define NTHREADS (WARPS_PER_CTA * 32)
#define ADMM_ITERS 200
#define FULLMASK 0xffffffffu

typedef unsigned long long u64;

// smem (floats): W1[32][257], w2[256], b1[256], per-warp: bufW[32],bufT[32],
// sA[24][36], sM[32][36]
#define SM_W1   (32 * 257)
#define SM_WARP (64 + 24 * 36 + 32 * 36)
#define SMEM_FLOATS (SM_W1 + 256 + 256 + WARPS_PER_CTA * SM_WARP)
#define SMEM_BYTES (SMEM_FLOATS * 4)

__device__ __forceinline__ void fma2(u64& d, u64 a, u64 b) {
    asm("fma.rn.f32x2 %0, %1, %2, %0;" : "+l"(d) : "l"(a), "l"(b));
}
__device__ __forceinline__ u64 add2(u64 a, u64 b) {
    u64 d; asm("add.rn.f32x2 %0, %1, %2;" : "=l"(d) : "l"(a), "l"(b)); return d;
}
__device__ __forceinline__ u64 pack2(float lo, float hi) {
    u64 d; asm("mov.b64 %0, {%1, %2};" : "=l"(d) : "f"(lo), "f"(hi)); return d;
}
__device__ __forceinline__ float2 unpack2(u64 v) {
    float2 f; asm("mov.b64 {%0, %1}, %2;" : "=f"(f.x), "=f"(f.y) : "l"(v)); return f;
}
__device__ __forceinline__ float hsum2(u64 a, u64 b) {
    float2 f = unpack2(add2(a, b)); return f.x + f.y;
}
__device__ __forceinline__ float bcast(float v, int lane) {
    return __shfl_sync(FULLMASK, v, lane & 31);
}

// In-place Gauss-Jordan inverse of SPD 32x32, row stride 36 floats (16B aligned
// rows; 36w stride => conflict-free per-lane float4 row access).
__device__ __forceinline__ void invert32(float* sM, int t) {
    #pragma unroll 1
    for (int k = 0; k < 32; k++) {
        float piv  = sM[k * 36 + k];
        float pinv = 1.0f / piv;
        float rk = sM[k * 36 + t] * pinv;
        if (t == k) rk = pinv;
        __syncwarp();
        sM[k * 36 + t] = rk;
        __syncwarp();
        if (t != k) {
            float f = sM[t * 36 + k];
            u64 fp = pack2(-f, -f);
            ulonglong2* rowT = reinterpret_cast<ulonglong2*>(sM + t * 36);
            const ulonglong2* rowK = reinterpret_cast<const ulonglong2*>(sM + k * 36);
            #pragma unroll
            for (int j4 = 0; j4 < 8; j4++) {
                ulonglong2 a = rowT[j4];
                ulonglong2 bb = rowK[j4];
                fma2(a.x, bb.x, fp);
                fma2(a.y, bb.y, fp);
                rowT[j4] = a;
            }
            sM[t * 36 + k] = -f * pinv;
        }
        __syncwarp();
    }
}

// Build S = sum_r scale_r * a_r a_r' + diag, invert, pack K rows and AK rows.
// Column t of A is re-read from sA (conflict-free) to avoid 24 persistent regs.
__device__ __forceinline__ void build_KA(float* sA, float* sM,
                                         int t, bool anchor, u64* Kp, u64* AKp)
{
    __syncwarp();   // prior readers of sM done
    // rank-1 accumulate column t of S (== row t, symmetric) in registers
    u64 Sp[16];
    #pragma unroll
    for (int i = 0; i < 16; i++) Sp[i] = 0ULL;
    #pragma unroll
    for (int r = 0; r < 24; r++) {
        float m = sA[r * 36 + t] * (anchor ? ((r < 20) ? 1.0f : 0.75f) : 1.0f);
        u64 mp = pack2(m, m);
        const ulonglong2* rowr = reinterpret_cast<const ulonglong2*>(sA + r * 36);
        #pragma unroll
        for (int j4 = 0; j4 < 8; j4++) {
            ulonglong2 a = rowr[j4];        // broadcast
            fma2(Sp[2 * j4],     a.x, mp);
            fma2(Sp[2 * j4 + 1], a.y, mp);
        }
    }
    ulonglong2* dst = reinterpret_cast<ulonglong2*>(sM + t * 36);
    #pragma unroll
    for (int j4 = 0; j4 < 8; j4++)
        dst[j4] = make_ulonglong2(Sp[2 * j4], Sp[2 * j4 + 1]);
    __syncwarp();
    sM[t * 36 + t] += anchor ? 2.0f : 1.0f;   // diag (conflict-free)
    __syncwarp();

    invert32(sM, t);                            // sM = K

    // Kp: lane t's row of K, as packed pairs
    {
        const ulonglong2* rowt = reinterpret_cast<const ulonglong2*>(sM + t * 36);
        #pragma unroll
        for (int j4 = 0; j4 < 8; j4++) {
            ulonglong2 a = rowt[j4];
            Kp[2 * j4] = a.x;  Kp[2 * j4 + 1] = a.y;
        }
    }
    // AK row t = sum_i A[t][i] * K[i][:]  (K rows broadcast from smem)
    float4 a4[8];
    {
        const float4* rowa = reinterpret_cast<const float4*>(sA + t * 36);
        #pragma unroll
        for (int j4 = 0; j4 < 8; j4++) a4[j4] = rowa[j4];
    }
    #pragma unroll
    for (int i = 0; i < 16; i++) AKp[i] = 0ULL;
    #pragma unroll
    for (int i = 0; i < 32; i++) {
        float ai = (i % 4 == 0) ? a4[i / 4].x : (i % 4 == 1) ? a4[i / 4].y
                 : (i % 4 == 2) ? a4[i / 4].z : a4[i / 4].w;
        u64 ap = pack2(ai, ai);
        const ulonglong2* rowk = reinterpret_cast<const ulonglong2*>(sM + i * 36);
        #pragma unroll
        for (int j4 = 0; j4 < 8; j4++) {
            ulonglong2 kk = rowk[j4];       // broadcast
            fma2(AKp[2 * j4],     kk.x, ap);
            fma2(AKp[2 * j4 + 1], kk.y, ap);
        }
    }
    if (t >= 24) {
        #pragma unroll
        for (int i = 0; i < 16; i++) AKp[i] = 0ULL;
    }
    __syncwarp();
}

__global__ __launch_bounds__(NTHREADS, 1)
void fw_kernel(const float* __restrict__ g_x,  const float* __restrict__ g_A,
               const float* __restrict__ g_b,  const float* __restrict__ g_W1,
               const float* __restrict__ g_b1, const float* __restrict__ g_w2,
               float* __restrict__ g_out, int nprob)
{
    extern __shared__ float smem[];
    float* sW1 = smem;
    float* sw2 = sW1 + SM_W1;
    float* sb1 = sw2 + 256;
    float* wsp = sb1 + 256;

    const int tid = threadIdx.x;
    const int wid = tid >> 5;
    const int t   = tid & 31;

    for (int i = tid; i < 32 * 256; i += NTHREADS)
        sW1[(i >> 8) * 257 + (i & 255)] = g_W1[i];
    for (int i = tid; i < 256; i += NTHREADS) { sw2[i] = g_w2[i]; sb1[i] = g_b1[i]; }
    __syncthreads();

    const int p = blockIdx.x * WARPS_PER_CTA + wid;
    if (p >= nprob) return;

    float* wbase = wsp + wid * SM_WARP;
    float* bufW = wbase;            // 32
    float* bufT = wbase + 32;       // 32
    float* sA   = wbase + 64;       // [24][36]
    float* sM   = sA + 24 * 36;     // [32][36]
    const ulonglong2* bW2 = reinterpret_cast<const ulonglong2*>(bufW);
    const ulonglong2* bT2 = reinterpret_cast<const ulonglong2*>(bufT);

    u64 Acolp[12], Kp[16], AKp[16];
    float Acq0, Acq1, Acq2, Acq3;
    {
        const float* Ap = g_A + (size_t)p * 768;    // [24][32]
        float Atmp[24];                              // short-lived
        #pragma unroll
        for (int r = 0; r < 24; r++) {
            float v = Ap[r * 32 + t];
            Atmp[r] = v;
            sA[r * 36 + t] = v;
        }
        #pragma unroll
        for (int c = 0; c < 12; c++) Acolp[c] = pack2(Atmp[2 * c], Atmp[2 * c + 1]);
        Acq0 = 0.25f * Atmp[20]; Acq1 = 0.25f * Atmp[21];
        Acq2 = 0.25f * Atmp[22]; Acq3 = 0.25f * Atmp[23];
    }
    const float h_hi = (t < 24) ? g_b[p * 24 + t] : 0.0f;
    const float xr   = g_x[(size_t)p * 32 + t];
    __syncwarp();

    // ================= anchor =================
    build_KA(sA, sM, t, true, Kp, AKp);

    float z_lo = 0.f, z_hi = 0.f, y_lo = 0.f, y_hi = 0.f;
    float x_feas;
    #pragma unroll 1
    for (int it = 0; it < ADMM_ITERS; it++) {
        bufW[t] = z_hi - y_hi;
        __syncwarp();
        ulonglong2 wv[7];
        #pragma unroll
        for (int j = 0; j < 7; j++) wv[j] = bW2[j];
        u64 r0 = 0ULL, r1 = 0ULL;
        #pragma unroll
        for (int c = 0; c < 6; c++) {
            fma2(r0, wv[c].x, Acolp[2 * c]);
            fma2(r1, wv[c].y, Acolp[2 * c + 1]);
        }
        float2 wA = unpack2(wv[5].x);   // w20,w21
        float2 wB = unpack2(wv[5].y);   // w22,w23
        float2 wC = unpack2(wv[6].x);   // w24,w25
        float2 wD = unpack2(wv[6].y);   // w26,w27
        float rs0 = -(wA.x + wC.x), rs1 = -(wA.y + wC.y);
        float rs2 = -(wB.x + wD.x), rs3 = -(wB.y + wD.y);
        float w_lo = z_lo - y_lo;
        float rx = (xr - w_lo) + hsum2(r0, r1);
        float tmp = rx + Acq0 * rs0 + Acq1 * rs1 + Acq2 * rs2 + Acq3 * rs3;
        bufT[t] = tmp;
        __syncwarp();
        u64 ua = 0ULL, ub = 0ULL, va = 0ULL, vb = 0ULL;
        #pragma unroll
        for (int j4 = 0; j4 < 8; j4++) {
            ulonglong2 tp = bT2[j4];
            fma2(ua, tp.x, Kp[2 * j4]);   fma2(ub, tp.y, Kp[2 * j4 + 1]);
            fma2(va, tp.x, AKp[2 * j4]);  fma2(vb, tp.y, AKp[2 * j4 + 1]);
        }
        float u = hsum2(ua, ub);
        float v = hsum2(va, vb);
        float rsel = (t & 2) ? ((t & 1) ? rs3 : rs2) : ((t & 1) ? rs1 : rs0);
        float vsh = __shfl_sync(FULLMASK, v, (t - 4) & 31);
        float Gu = (t < 20) ? v
                 : (t < 24) ? (0.75f * v - 0.25f * rsel)
                 : (t < 28) ? (-0.25f * (rsel + vsh)) : 0.0f;
        float zn = fminf(Gu + y_hi, h_hi);  y_hi += Gu - zn;  z_hi = zn;
        float zl = fminf(y_lo - u, 0.0f);   y_lo += (-u) - zl; z_lo = zl;
    }
    {   // final half-step
        bufW[t] = z_hi - y_hi;
        __syncwarp();
        ulonglong2 wv[7];
        #pragma unroll
        for (int j = 0; j < 7; j++) wv[j] = bW2[j];
        u64 r0 = 0ULL, r1 = 0ULL;
        #pragma unroll
        for (int c = 0; c < 6; c++) {
            fma2(r0, wv[c].x, Acolp[2 * c]);
            fma2(r1, wv[c].y, Acolp[2 * c + 1]);
        }
        float2 wA = unpack2(wv[5].x), wB = unpack2(wv[5].y);
        float2 wC = unpack2(wv[6].x), wD = unpack2(wv[6].y);
        float rs0 = -(wA.x + wC.x), rs1 = -(wA.y + wC.y);
        float rs2 = -(wB.x + wD.x), rs3 = -(wB.y + wD.y);
        float w_lo = z_lo - y_lo;
        float rx = (xr - w_lo) + hsum2(r0, r1);
        float tmp = rx + Acq0 * rs0 + Acq1 * rs1 + Acq2 * rs2 + Acq3 * rs3;
        bufT[t] = tmp;
        __syncwarp();
        u64 ua = 0ULL, ub = 0ULL;
        #pragma unroll
        for (int j4 = 0; j4 < 8; j4++) {
            ulonglong2 tp = bT2[j4];
            fma2(ua, tp.x, Kp[2 * j4]);  fma2(ub, tp.y, Kp[2 * j4 + 1]);
        }
        x_feas = hsum2(ua, ub);
    }

    // ================= critic gradient =================
    float gsum = 0.f;
    {
        float pre[8];
        #pragma unroll
        for (int k2 = 0; k2 < 8; k2++) pre[k2] = sb1[k2 * 32 + t];
        #pragma unroll 1
        for (int n = 0; n < 32; n++) {
            float xv = bcast(x_feas, n);
            #pragma unroll
            for (int k2 = 0; k2 < 8; k2++)
                pre[k2] += sW1[n * 257 + k2 * 32 + t] * xv;
        }
        float coef[8];
        #pragma unroll
        for (int k2 = 0; k2 < 8; k2++) {
            float th = tanhf(pre[k2]);
            coef[k2] = sw2[k2 * 32 + t] * (1.0f - th * th);
        }
        #pragma unroll 1
        for (int l = 0; l < 32; l++) {
            #pragma unroll
            for (int k2 = 0; k2 < 8; k2++)
                gsum += sW1[t * 257 + k2 * 32 + l] * bcast(coef[k2], l);
        }
    }

    // ================= lmo =================
    build_KA(sA, sM, t, false, Kp, AKp);

    z_lo = 0.f; z_hi = 0.f; y_lo = 0.f; y_hi = 0.f;
    float c_sol;
    #pragma unroll 1
    for (int it = 0; it < ADMM_ITERS; it++) {
        bufW[t] = z_hi - y_hi;
        __syncwarp();
        ulonglong2 wv[6];
        #pragma unroll
        for (int j = 0; j < 6; j++) wv[j] = bW2[j];
        u64 r0 = 0ULL, r1 = 0ULL;
        #pragma unroll
        for (int c = 0; c < 6; c++) {
            fma2(r0, wv[c].x, Acolp[2 * c]);
            fma2(r1, wv[c].y, Acolp[2 * c + 1]);
        }
        float w_lo = z_lo - y_lo;
        float rhs = (gsum - w_lo) + hsum2(r0, r1);
        bufT[t] = rhs;
        __syncwarp();
        u64 ua = 0ULL, ub = 0ULL, va = 0ULL, vb = 0ULL;
        #pragma unroll
        for (int j4 = 0; j4 < 8; j4++) {
            ulonglong2 tp = bT2[j4];
            fma2(ua, tp.x, Kp[2 * j4]);   fma2(ub, tp.y, Kp[2 * j4 + 1]);
            fma2(va, tp.x, AKp[2 * j4]);  fma2(vb, tp.y, AKp[2 * j4 + 1]);
        }
        float u = hsum2(ua, ub);
        float v = hsum2(va, vb);
        float zn = fminf(v + y_hi, h_hi);  y_hi += v - zn;   z_hi = zn;
        float zl = fminf(y_lo - u, 0.0f);  y_lo += (-u) - zl; z_lo = zl;
    }
    {   // final half-step
        bufW[t] = z_hi - y_hi;
        __syncwarp();
        ulonglong2 wv[6];
        #pragma unroll
        for (int j = 0; j < 6; j++) wv[j] = bW2[j];
        u64 r0 = 0ULL, r1 = 0ULL;
        #pragma unroll
        for (int c = 0; c < 6; c++) {
            fma2(r0, wv[c].x, Acolp[2 * c]);
            fma2(r1, wv[c].y, Acolp[2 * c + 1]);
        }
        float w_lo = z_lo - y_lo;
        float rhs = (gsum - w_lo) + hsum2(r0, r1);
        bufT[t] = rhs;
        __syncwarp();
        u64 ua = 0ULL, ub = 0ULL;
        #pragma unroll
        for (int j4 = 0; j4 < 8; j4++) {
            ulonglong2 tp = bT2[j4];
            fma2(ua, tp.x, Kp[2 * j4]);  fma2(ub, tp.y, Kp[2 * j4 + 1]);
        }
        c_sol = hsum2(ua, ub);
    }

    g_out[(size_t)p * 32 + t] = 0.9f * x_feas + 0.1f * c_sol;
}

extern "C" void kernel_launch(void* const* d_in, const int* in_sizes, int n_in,
                              void* d_out, int out_size)
{
    const float* x  = (const float*)d_in[0];
    const float* A  = (const float*)d_in[1];
    const float* b  = (const float*)d_in[2];
    const float* W1 = (const float*)d_in[3];
    const float* b1 = (const float*)d_in[4];
    const float* w2 = (const float*)d_in[5];

    int nprob = in_sizes[0] / 32;
    cudaFuncSetAttribute(fw_kernel, cudaFuncAttributeMaxDynamicSharedMemorySize,
                         SMEM_BYTES);
    int grid = (nprob + WARPS_PER_CTA - 1) / WARPS_PER_CTA;
    fw_kernel<<<grid, NTHREADS, SMEM_BYTES>>>(x, A, b, W1, b1, w2,
                                              (float*)d_out, nprob);
}